// round 7
// baseline (speedup 1.0000x reference)
#include <cuda_runtime.h>
#include <cuda_fp16.h>
#include <math.h>
#include <stdint.h>

// Problem constants
#define Bsz  16
#define Ssz  2048
#define Esz  512
#define Hsz  512
#define HIsz 1024
#define Lsz  3
#define Msz  (Bsz * Ssz)
#define Vsz  32000

// ---------------------------------------------------------------------------
// Scratch (__device__ globals; allocation-free)
// ---------------------------------------------------------------------------
__device__ __half g_x16f[(size_t)Msz * Hsz];
__device__ __half g_x16r[(size_t)Msz * Hsz];
__device__ __half g_hg16f[(size_t)Msz * 2 * HIsz];
__device__ __half g_hg16r[(size_t)Msz * 2 * HIsz];
__device__ __half g_h16f[(size_t)Msz * HIsz];
__device__ __half g_h16r[(size_t)Msz * HIsz];
__device__ __half g_emb16[(size_t)Vsz * Esz];
#define NWELEM 9699328
__device__ __half g_w16[NWELEM];

#define OFF_ER    0
#define OFF_HGF   262144
#define OFF_OUTF  3407872
#define OFF_HGR   4980736
#define OFF_OUTR  8126464

// ---------------------------------------------------------------------------
// PTX helpers (baseline sm_103 ISA only)
// ---------------------------------------------------------------------------
__device__ __forceinline__ uint32_t s2u(const void* p) {
    uint32_t a;
    asm("{ .reg .u64 t; cvta.to.shared.u64 t, %1; cvt.u32.u64 %0, t; }" : "=r"(a) : "l"(p));
    return a;
}
__device__ __forceinline__ void cp16(uint32_t d, const void* s) {
    asm volatile("cp.async.cg.shared.global [%0], [%1], 16;" :: "r"(d), "l"(s));
}
__device__ __forceinline__ void cp_commit() { asm volatile("cp.async.commit_group;"); }
__device__ __forceinline__ void cp_wait2()  { asm volatile("cp.async.wait_group 2;"); }
__device__ __forceinline__ void ldm_x4(uint32_t addr, uint32_t& r0, uint32_t& r1,
                                       uint32_t& r2, uint32_t& r3) {
    asm volatile("ldmatrix.sync.aligned.m8n8.x4.shared.b16 {%0,%1,%2,%3}, [%4];"
                 : "=r"(r0), "=r"(r1), "=r"(r2), "=r"(r3) : "r"(addr));
}
__device__ __forceinline__ void mma_fp16(float& c0, float& c1, float& c2, float& c3,
                                         uint32_t a0, uint32_t a1, uint32_t a2, uint32_t a3,
                                         uint32_t b0, uint32_t b1) {
    asm volatile("mma.sync.aligned.m16n8k16.row.col.f32.f16.f16.f32 "
                 "{%0,%1,%2,%3}, {%4,%5,%6,%7}, {%8,%9}, {%0,%1,%2,%3};"
                 : "+f"(c0), "+f"(c1), "+f"(c2), "+f"(c3)
                 : "r"(a0), "r"(a1), "r"(a2), "r"(a3), "r"(b0), "r"(b1));
}

__device__ __forceinline__ int revrow(int r, int len) {
    int s = r & (Ssz - 1);
    int t = s + Ssz - len; if (t >= Ssz) t -= Ssz;
    return (r & ~(Ssz - 1)) + (Ssz - 1 - t);
}

// ---------------------------------------------------------------------------
// fp16 GEMM, dual-problem batched over blockIdx.z.
// CTA tile 128x256, warp tile 64x64 (8 warps 2x4), BK=32, 4-stage cp.async.
// ---------------------------------------------------------------------------
struct GArgs {
    const __half* A;
    const __half* B;
    float*        C32;
    __half*       C16;
    __half*       C16b;
    const float*  bias;
    const int*    rowidx;
    const int*    lens;
    int cstride;
    int coloff;
    int c32rev;
};

#define GT 256
#define ROWB 80
#define TILE_A_B (128 * ROWB)               // 10240 B
#define TILE_BB  (256 * ROWB)               // 20480 B
#define STAGE_B (TILE_A_B + TILE_BB)        // 30720 B
#define GSM (4 * STAGE_B)                   // 122880 B

__global__ __launch_bounds__(GT, 1)
void gemm_kernel(GArgs ga0, GArgs ga1, int N, int K)
{
    extern __shared__ char smem[];
    const uint32_t sbase = s2u(smem);
    const GArgs ga = blockIdx.z ? ga1 : ga0;

    const int tid = threadIdx.x;
    const int wid = tid >> 5, lid = tid & 31;
    const int bm = blockIdx.y * 128, bn = blockIdx.x * 256;
    const int wm = (wid & 1) * 64;
    const int wn = (wid >> 1) * 64;

    // cp.async slots: 6 x 16B per thread (A 512 + B 1024 chunks)
    const __half* gsrc[6];
    uint32_t soff[6];
#pragma unroll
    for (int j = 0; j < 6; j++) {
        int cidx = tid + j * GT;              // 0..1535
        if (cidx < 512) {
            int row = cidx >> 2, seg = cidx & 3;
            soff[j] = (uint32_t)(row * ROWB + seg * 16);
            long ra = ga.rowidx ? (long)ga.rowidx[bm + row] : (long)(bm + row);
            gsrc[j] = ga.A + ra * (long)K + seg * 8;
        } else {
            int idx = cidx - 512;             // 0..1023
            int row = idx >> 2, seg = idx & 3;
            soff[j] = (uint32_t)(TILE_A_B + row * ROWB + seg * 16);
            gsrc[j] = ga.B + (long)(bn + row) * K + seg * 8;
        }
    }

    uint32_t aoff[4];
#pragma unroll
    for (int mt = 0; mt < 4; mt++) {
        int r = wm + mt * 16 + (lid & 15);
        int c = (lid >> 4) * 8;
        aoff[mt] = (uint32_t)(r * ROWB + c * 2);
    }
    uint32_t boff[4];
#pragma unroll
    for (int np = 0; np < 4; np++) {
        int r = wn + np * 16 + (lid & 7) + ((lid >> 4) << 3);
        int c = ((lid >> 3) & 1) * 8;
        boff[np] = (uint32_t)(TILE_A_B + r * ROWB + c * 2);
    }

    float acc[4][8][4];
#pragma unroll
    for (int i = 0; i < 4; i++)
#pragma unroll
        for (int j = 0; j < 8; j++)
#pragma unroll
            for (int q = 0; q < 4; q++) acc[i][j][q] = 0.f;

    const int nst = K >> 5;

    auto load_stage = [&](int s) {
        uint32_t base = sbase + (uint32_t)(s & 3) * STAGE_B;
        int ko = s << 5;
#pragma unroll
        for (int j = 0; j < 6; j++) cp16(base + soff[j], gsrc[j] + ko);
    };

    load_stage(0); cp_commit();
    load_stage(1); cp_commit();
    load_stage(2); cp_commit();

    for (int s = 0; s < nst; s++) {
        cp_wait2();
        __syncthreads();
        if (s + 3 < nst) load_stage(s + 3);
        cp_commit();

        uint32_t base = sbase + (uint32_t)(s & 3) * STAGE_B;
#pragma unroll
        for (int k16 = 0; k16 < 2; k16++) {
            uint32_t koff = (uint32_t)(k16 * 32);
            uint32_t af[4][4];
#pragma unroll
            for (int mt = 0; mt < 4; mt++)
                ldm_x4(base + aoff[mt] + koff, af[mt][0], af[mt][1], af[mt][2], af[mt][3]);
            uint32_t bf[8][2];
#pragma unroll
            for (int np = 0; np < 4; np++) {
                uint32_t r0, r1, r2, r3;
                ldm_x4(base + boff[np] + koff, r0, r1, r2, r3);
                bf[np * 2][0] = r0;     bf[np * 2][1] = r1;
                bf[np * 2 + 1][0] = r2; bf[np * 2 + 1][1] = r3;
            }
#pragma unroll
            for (int mt = 0; mt < 4; mt++)
#pragma unroll
                for (int nt = 0; nt < 8; nt++)
                    mma_fp16(acc[mt][nt][0], acc[mt][nt][1], acc[mt][nt][2], acc[mt][nt][3],
                             af[mt][0], af[mt][1], af[mt][2], af[mt][3],
                             bf[nt][0], bf[nt][1]);
        }
    }

    // ---- epilogue ----
    int len = ga.lens ? ga.lens[bm >> 11] : 0;
#pragma unroll
    for (int mt = 0; mt < 4; mt++) {
        int rA = bm + wm + mt * 16 + (lid >> 2);
        int rB = rA + 8;
        int rAm = ga.lens ? revrow(rA, len) : 0;
        int rBm = ga.lens ? revrow(rB, len) : 0;
#pragma unroll
        for (int nt = 0; nt < 8; nt++) {
            int col = bn + wn + nt * 8 + (lid & 3) * 2;
            float v0 = acc[mt][nt][0], v1 = acc[mt][nt][1];
            float v2 = acc[mt][nt][2], v3 = acc[mt][nt][3];
            if (ga.bias) {
                float2 bb = *(const float2*)(ga.bias + col);
                v0 += bb.x; v1 += bb.y; v2 += bb.x; v3 += bb.y;
            }
            if (ga.C32) {
                int wA = ga.c32rev ? rAm : rA;
                int wB = ga.c32rev ? rBm : rB;
                *(float2*)(ga.C32 + (size_t)wA * ga.cstride + ga.coloff + col) = make_float2(v0, v1);
                *(float2*)(ga.C32 + (size_t)wB * ga.cstride + ga.coloff + col) = make_float2(v2, v3);
            }
            if (ga.C16) {
                *(__half2*)(ga.C16 + (size_t)rA * ga.cstride + col) = __floats2half2_rn(v0, v1);
                *(__half2*)(ga.C16 + (size_t)rB * ga.cstride + col) = __floats2half2_rn(v2, v3);
            }
            if (ga.C16b) {
                *(__half2*)(ga.C16b + (size_t)rAm * ga.cstride + col) = __floats2half2_rn(v0, v1);
                *(__half2*)(ga.C16b + (size_t)rBm * ga.cstride + col) = __floats2half2_rn(v2, v3);
            }
        }
    }
}

// ---------------------------------------------------------------------------
// weight transpose+convert
// ---------------------------------------------------------------------------
__global__ void wconv_batch_kernel(const float* __restrict__ Wf, const float* __restrict__ Wr,
                                   __half* __restrict__ Tf, __half* __restrict__ Tr,
                                   int K, int N)
{
    __shared__ float t[32][33];
    int z = blockIdx.z;
    int l = (z >= 3) ? z - 3 : z;
    const float* W = ((z >= 3) ? Wr : Wf) + (size_t)l * K * N;
    __half*      T = ((z >= 3) ? Tr : Tf) + (size_t)l * K * N;
    int n0 = blockIdx.x * 32, k0 = blockIdx.y * 32;
    int tx = threadIdx.x, ty = threadIdx.y;
    for (int r = ty; r < 32; r += 8)
        t[r][tx] = W[(size_t)(k0 + r) * N + n0 + tx];
    __syncthreads();
    for (int r = ty; r < 32; r += 8)
        T[(size_t)(n0 + r) * K + k0 + tx] = __float2half(t[tx][r]);
}

__global__ void wconv_kernel(const float* __restrict__ W, __half* __restrict__ T,
                             int K, int N)
{
    __shared__ float t[32][33];
    int n0 = blockIdx.x * 32, k0 = blockIdx.y * 32;
    int tx = threadIdx.x, ty = threadIdx.y;
    for (int r = ty; r < 32; r += 8)
        t[r][tx] = W[(size_t)(k0 + r) * N + n0 + tx];
    __syncthreads();
    for (int r = ty; r < 32; r += 8)
        T[(size_t)(n0 + r) * K + k0 + tx] = __float2half(t[tx][r]);
}

__global__ void conv_kernel(const float* __restrict__ x, __half* __restrict__ y, size_t n)
{
    size_t i = ((size_t)blockIdx.x * blockDim.x + threadIdx.x) * 8;
    if (i >= n) return;
    float4 a = *(const float4*)(x + i);
    float4 b = *(const float4*)(x + i + 4);
    struct alignas(16) H8 { __half2 d[4]; } o;
    o.d[0] = __floats2half2_rn(a.x, a.y);
    o.d[1] = __floats2half2_rn(a.z, a.w);
    o.d[2] = __floats2half2_rn(b.x, b.y);
    o.d[3] = __floats2half2_rn(b.z, b.w);
    *(H8*)(y + i) = o;
}

// ---------------------------------------------------------------------------
// Linear minGRU scan — cp.async smem-pipelined streaming version.
// ---------------------------------------------------------------------------
#define SCT 16
#define SSTAGE_B 8192

__global__ __launch_bounds__(128, 2)
void scan_kernel(const __half* __restrict__ hgF, const __half* __restrict__ hgR,
                 __half* __restrict__ hF, __half* __restrict__ hR)
{
    __shared__ char smem[4 * SSTAGE_B];
    const uint32_t sb = s2u(smem);
    const int tid = threadIdx.x;
    const int b = blockIdx.x >> 3;
    const int cblk = (blockIdx.x & 7) << 7;
    const int c = cblk + tid;
    const int dir = blockIdx.y;

    const __half* hgp = (dir ? hgR : hgF) + (size_t)b * Ssz * 2 * HIsz;
    __half* hp = (dir ? hR : hF) + (size_t)b * Ssz * HIsz + c;

    const __half* gsl[4];
    uint32_t ssl[4];
#pragma unroll
    for (int j = 0; j < 4; j++) {
        int lin = tid + 128 * j;
        int u   = lin >> 5;
        int prt = lin & 31;
        int isg = prt >> 4;
        int seg = prt & 15;
        gsl[j] = hgp + (size_t)u * 2 * HIsz + (size_t)isg * HIsz + cblk + seg * 8;
        ssl[j] = (uint32_t)(u * 512 + isg * 256 + seg * 16);
    }

    auto load_stage = [&](int st) {
        uint32_t base = sb + (uint32_t)(st & 3) * SSTAGE_B;
        size_t go = (size_t)st * SCT * 2 * HIsz;
#pragma unroll
        for (int j = 0; j < 4; j++) cp16(base + ssl[j], gsl[j] + go);
        cp_commit();
    };

    load_stage(0);
    load_stage(1);
    load_stage(2);

    const int NST = Ssz / SCT;
    float h = 0.f;
    for (int st = 0; st < NST; st++) {
        cp_wait2();
        __syncthreads();
        if (st + 3 < NST) load_stage(st + 3);

        const __half* base = (const __half*)(smem + (size_t)(st & 3) * SSTAGE_B);
#pragma unroll
        for (int u = 0; u < SCT; u++) {
            float hid  = __half2float(base[u * 256 + tid]);
            float gate = __half2float(base[u * 256 + 128 + tid]);
            float z = __fdividef(1.f, 1.f + __expf(-gate));
            float g = (hid >= 0.f) ? (hid + 0.5f)
                                   : __fdividef(1.f, 1.f + __expf(-hid));
            h += z * (g - h);
            hp[(size_t)(st * SCT + u) * HIsz] = __float2half(h);
        }
    }
}

// ---------------------------------------------------------------------------
__global__ void seq_kernel(const float* __restrict__ out, const int* __restrict__ lens,
                           float* __restrict__ seq)
{
    int b = blockIdx.x;
    int len = lens[b];
    const float* row = out + ((size_t)b * Ssz + (len - 1)) * 2 * Hsz;
    for (int j = threadIdx.x; j < 2 * Hsz; j += blockDim.x)
        seq[(size_t)b * 2 * Hsz + j] = row[j];
}

// ---------------------------------------------------------------------------
extern "C" void kernel_launch(void* const* d_in, const int* in_sizes, int n_in,
                              void* d_out, int out_size)
{
    const int*   x_source  = (const int*)  d_in[0];
    const int*   x_lengths = (const int*)  d_in[1];
    const float* emb       = (const float*)d_in[2];
    const float* W_er      = (const float*)d_in[3];
    const float* b_er      = (const float*)d_in[4];
    const float* Whg_f     = (const float*)d_in[5];
    const float* Wout_f    = (const float*)d_in[6];
    const float* Whg_r     = (const float*)d_in[7];
    const float* Wout_r    = (const float*)d_in[8];
    float* out = (float*)d_out;

    __half *x16f, *x16r, *hg16f, *hg16r, *h16f, *h16r, *emb16, *w16;
    cudaGetSymbolAddress((void**)&x16f,  g_x16f);
    cudaGetSymbolAddress((void**)&x16r,  g_x16r);
    cudaGetSymbolAddress((void**)&hg16f, g_hg16f);
    cudaGetSymbolAddress((void**)&hg16r, g_hg16r);
    cudaGetSymbolAddress((void**)&h16f,  g_h16f);
    cudaGetSymbolAddress((void**)&h16r,  g_h16r);
    cudaGetSymbolAddress((void**)&emb16, g_emb16);
    cudaGetSymbolAddress((void**)&w16,   g_w16);

    cudaFuncSetAttribute(gemm_kernel, cudaFuncAttributeMaxDynamicSharedMemorySize, GSM);

    // weight converts
    wconv_batch_kernel<<<dim3(2 * HIsz / 32, Hsz / 32, 6), dim3(32, 8)>>>(
        Whg_f, Whg_r, w16 + OFF_HGF, w16 + OFF_HGR, Hsz, 2 * HIsz);
    wconv_batch_kernel<<<dim3(Hsz / 32, HIsz / 32, 6), dim3(32, 8)>>>(
        Wout_f, Wout_r, w16 + OFF_OUTF, w16 + OFF_OUTR, HIsz, Hsz);
    wconv_kernel<<<dim3(Hsz / 32, Esz / 32), dim3(32, 8)>>>(W_er, w16 + OFF_ER, Esz, Hsz);
    conv_kernel<<<(unsigned)(((size_t)Vsz * Esz) / 2048), 256>>>(emb, emb16, (size_t)Vsz * Esz);

    // embed GEMM -> x16f and rev-rotated x16r (fused)
    {
        GArgs a0 = { emb16, w16 + OFF_ER, nullptr, x16f, x16r, b_er, x_source, x_lengths,
                     Hsz, 0, 0 };
        gemm_kernel<<<dim3(Hsz / 256, Msz / 128, 1), GT, GSM>>>(a0, a0, Hsz, Esz);
    }

    for (int l = 0; l < Lsz; l++) {
        bool last = (l == Lsz - 1);
        {
            GArgs a0 = { x16f, w16 + OFF_HGF + (size_t)l * 1048576, nullptr, hg16f, nullptr,
                         nullptr, nullptr, nullptr, 2 * HIsz, 0, 0 };
            GArgs a1 = { x16r, w16 + OFF_HGR + (size_t)l * 1048576, nullptr, hg16r, nullptr,
                         nullptr, nullptr, nullptr, 2 * HIsz, 0, 0 };
            gemm_kernel<<<dim3(2 * HIsz / 256, Msz / 128, 2), GT, GSM>>>(a0, a1, 2 * HIsz, Hsz);
        }
        scan_kernel<<<dim3(128, 2), 128>>>(hg16f, hg16r, h16f, h16r);
        if (!last) {
            GArgs a0 = { h16f, w16 + OFF_OUTF + (size_t)l * 524288, nullptr, x16f, nullptr,
                         nullptr, nullptr, nullptr, Hsz, 0, 0 };
            GArgs a1 = { h16r, w16 + OFF_OUTR + (size_t)l * 524288, nullptr, x16r, nullptr,
                         nullptr, nullptr, nullptr, Hsz, 0, 0 };
            gemm_kernel<<<dim3(Hsz / 256, Msz / 128, 2), GT, GSM>>>(a0, a1, Hsz, HIsz);
        } else {
            GArgs a0 = { h16f, w16 + OFF_OUTF + (size_t)l * 524288, out, nullptr, nullptr,
                         nullptr, nullptr, x_lengths, 2 * Hsz, 0, 0 };
            GArgs a1 = { h16r, w16 + OFF_OUTR + (size_t)l * 524288, out, nullptr, nullptr,
                         nullptr, nullptr, x_lengths, 2 * Hsz, Hsz, 1 };
            gemm_kernel<<<dim3(Hsz / 256, Msz / 128, 2), GT, GSM>>>(a0, a1, Hsz, HIsz);
        }
    }

    long long need = (long long)Msz * 2 * Hsz + (long long)Bsz * 2 * Hsz;
    if ((long long)out_size >= need)
        seq_kernel<<<Bsz, 256>>>(out, x_lengths, out + (size_t)Msz * 2 * Hsz);
}

// round 10
// speedup vs baseline: 1.0572x; 1.0572x over previous
#include <cuda_runtime.h>
#include <cuda_fp16.h>
#include <math.h>
#include <stdint.h>

// Problem constants
#define Bsz  16
#define Ssz  2048
#define Esz  512
#define Hsz  512
#define HIsz 1024
#define Lsz  3
#define Msz  (Bsz * Ssz)
#define Vsz  32000

// ---------------------------------------------------------------------------
// Scratch (__device__ globals; allocation-free)
// ---------------------------------------------------------------------------
__device__ __half g_x16f[(size_t)Msz * Hsz];
__device__ __half g_x16r[(size_t)Msz * Hsz];
__device__ __half g_hg16f[(size_t)Msz * 2 * HIsz];   // (gate, v) interleaved pairs
__device__ __half g_hg16r[(size_t)Msz * 2 * HIsz];
__device__ __half g_h16f[(size_t)Msz * HIsz];
__device__ __half g_h16r[(size_t)Msz * HIsz];
__device__ __half g_emb16[(size_t)Vsz * Esz];
#define NWELEM 9699328
__device__ __half g_w16[NWELEM];

#define OFF_ER    0
#define OFF_HGF   262144
#define OFF_OUTF  3407872
#define OFF_HGR   4980736
#define OFF_OUTR  8126464

// ---------------------------------------------------------------------------
// PTX helpers (baseline sm_103 ISA only)
// ---------------------------------------------------------------------------
__device__ __forceinline__ uint32_t s2u(const void* p) {
    uint32_t a;
    asm("{ .reg .u64 t; cvta.to.shared.u64 t, %1; cvt.u32.u64 %0, t; }" : "=r"(a) : "l"(p));
    return a;
}
__device__ __forceinline__ void cp16(uint32_t d, const void* s) {
    asm volatile("cp.async.cg.shared.global [%0], [%1], 16;" :: "r"(d), "l"(s));
}
__device__ __forceinline__ void cp_commit() { asm volatile("cp.async.commit_group;"); }
__device__ __forceinline__ void cp_wait2()  { asm volatile("cp.async.wait_group 2;"); }
__device__ __forceinline__ void ldm_x4(uint32_t addr, uint32_t& r0, uint32_t& r1,
                                       uint32_t& r2, uint32_t& r3) {
    asm volatile("ldmatrix.sync.aligned.m8n8.x4.shared.b16 {%0,%1,%2,%3}, [%4];"
                 : "=r"(r0), "=r"(r1), "=r"(r2), "=r"(r3) : "r"(addr));
}
__device__ __forceinline__ void mma_fp16(float& c0, float& c1, float& c2, float& c3,
                                         uint32_t a0, uint32_t a1, uint32_t a2, uint32_t a3,
                                         uint32_t b0, uint32_t b1) {
    asm volatile("mma.sync.aligned.m16n8k16.row.col.f32.f16.f16.f32 "
                 "{%0,%1,%2,%3}, {%4,%5,%6,%7}, {%8,%9}, {%0,%1,%2,%3};"
                 : "+f"(c0), "+f"(c1), "+f"(c2), "+f"(c3)
                 : "r"(a0), "r"(a1), "r"(a2), "r"(a3), "r"(b0), "r"(b1));
}

__device__ __forceinline__ int revrow(int r, int len) {
    int s = r & (Ssz - 1);
    int t = s + Ssz - len; if (t >= Ssz) t -= Ssz;
    return (r & ~(Ssz - 1)) + (Ssz - 1 - t);
}

// (hid, gate) -> (gate, v = z*g); c recomputed fp32 in the scan
__device__ __forceinline__ float2 scanprep(float hid, float gate) {
    float z = __fdividef(1.f, 1.f + __expf(-gate));
    float g = (hid >= 0.f) ? (hid + 0.5f) : __fdividef(1.f, 1.f + __expf(-hid));
    return make_float2(gate, z * g);
}

// ---------------------------------------------------------------------------
// fp16 GEMM (round-6 config), dual-problem batched over blockIdx.z.
// Tile 128x128, BK=32, 8 warps (warp tile 64x32), 4-stage cp.async.
// sprep=1: columns are interleaved (hid,gate) pairs; epilogue writes (gate,v).
// ---------------------------------------------------------------------------
struct GArgs {
    const __half* A;
    const __half* B;
    float*        C32;
    __half*       C16;
    __half*       C16b;
    const float*  bias;
    const int*    rowidx;
    const int*    lens;
    int cstride;
    int coloff;
    int c32rev;
    int sprep;
};

#define GT 256
#define ROWB 80
#define TILE_B (128 * ROWB)
#define STAGE_B (2 * TILE_B)
#define GSM (4 * STAGE_B)

__global__ __launch_bounds__(GT, 2)
void gemm_kernel(GArgs ga0, GArgs ga1, int N, int K)
{
    extern __shared__ char smem[];
    const uint32_t sbase = s2u(smem);
    const GArgs ga = blockIdx.z ? ga1 : ga0;

    const int tid = threadIdx.x;
    const int wid = tid >> 5, lid = tid & 31;
    const int bm = blockIdx.y * 128, bn = blockIdx.x * 128;
    const int wm = (wid & 1) * 64;
    const int wn = (wid >> 1) * 32;

    const __half* gsrc[4];
    uint32_t soff[4];
#pragma unroll
    for (int j = 0; j < 4; j++) {
        int cidx = tid + j * GT;
        int tile = cidx >> 9;
        int idx  = cidx & 511;
        int row  = idx >> 2;
        int seg  = idx & 3;
        soff[j] = (uint32_t)(tile * TILE_B + row * ROWB + seg * 16);
        if (tile == 0) {
            long ra = ga.rowidx ? (long)ga.rowidx[bm + row] : (long)(bm + row);
            gsrc[j] = ga.A + ra * (long)K + seg * 8;
        } else {
            gsrc[j] = ga.B + (long)(bn + row) * K + seg * 8;
        }
    }

    uint32_t aoff[4];
#pragma unroll
    for (int mt = 0; mt < 4; mt++) {
        int r = wm + mt * 16 + (lid & 15);
        int c = (lid >> 4) * 8;
        aoff[mt] = (uint32_t)(r * ROWB + c * 2);
    }
    uint32_t boff[2];
#pragma unroll
    for (int np = 0; np < 2; np++) {
        int r = wn + np * 16 + (lid & 7) + ((lid >> 4) << 3);
        int c = ((lid >> 3) & 1) * 8;
        boff[np] = (uint32_t)(TILE_B + r * ROWB + c * 2);
    }

    float acc[4][4][4];
#pragma unroll
    for (int i = 0; i < 4; i++)
#pragma unroll
        for (int j = 0; j < 4; j++)
#pragma unroll
            for (int q = 0; q < 4; q++) acc[i][j][q] = 0.f;

    const int nst = K >> 5;

    auto load_stage = [&](int s) {
        uint32_t base = sbase + (uint32_t)(s & 3) * STAGE_B;
        int ko = s << 5;
#pragma unroll
        for (int j = 0; j < 4; j++) cp16(base + soff[j], gsrc[j] + ko);
    };

    load_stage(0); cp_commit();
    load_stage(1); cp_commit();
    load_stage(2); cp_commit();

    for (int s = 0; s < nst; s++) {
        cp_wait2();
        __syncthreads();
        if (s + 3 < nst) load_stage(s + 3);
        cp_commit();

        uint32_t base = sbase + (uint32_t)(s & 3) * STAGE_B;
#pragma unroll
        for (int k16 = 0; k16 < 2; k16++) {
            uint32_t koff = (uint32_t)(k16 * 32);
            uint32_t af[4][4];
#pragma unroll
            for (int mt = 0; mt < 4; mt++)
                ldm_x4(base + aoff[mt] + koff, af[mt][0], af[mt][1], af[mt][2], af[mt][3]);
            uint32_t bf[4][2];
#pragma unroll
            for (int np = 0; np < 2; np++) {
                uint32_t r0, r1, r2, r3;
                ldm_x4(base + boff[np] + koff, r0, r1, r2, r3);
                bf[np * 2][0] = r0;     bf[np * 2][1] = r1;
                bf[np * 2 + 1][0] = r2; bf[np * 2 + 1][1] = r3;
            }
#pragma unroll
            for (int mt = 0; mt < 4; mt++)
#pragma unroll
                for (int nt = 0; nt < 4; nt++)
                    mma_fp16(acc[mt][nt][0], acc[mt][nt][1], acc[mt][nt][2], acc[mt][nt][3],
                             af[mt][0], af[mt][1], af[mt][2], af[mt][3],
                             bf[nt][0], bf[nt][1]);
        }
    }

    // ---- epilogue ----
    int len = ga.lens ? ga.lens[bm >> 11] : 0;
#pragma unroll
    for (int mt = 0; mt < 4; mt++) {
        int rA = bm + wm + mt * 16 + (lid >> 2);
        int rB = rA + 8;
        int rAm = ga.lens ? revrow(rA, len) : 0;
        int rBm = ga.lens ? revrow(rB, len) : 0;
#pragma unroll
        for (int nt = 0; nt < 4; nt++) {
            int col = bn + wn + nt * 8 + (lid & 3) * 2;
            float v0 = acc[mt][nt][0], v1 = acc[mt][nt][1];
            float v2 = acc[mt][nt][2], v3 = acc[mt][nt][3];
            if (ga.bias) {
                float2 bb = *(const float2*)(ga.bias + col);
                v0 += bb.x; v1 += bb.y; v2 += bb.x; v3 += bb.y;
            }
            if (ga.sprep) {
                float2 cv0 = scanprep(v0, v1);
                float2 cv1 = scanprep(v2, v3);
                v0 = cv0.x; v1 = cv0.y; v2 = cv1.x; v3 = cv1.y;
            }
            if (ga.C32) {
                int wA = ga.c32rev ? rAm : rA;
                int wB = ga.c32rev ? rBm : rB;
                *(float2*)(ga.C32 + (size_t)wA * ga.cstride + ga.coloff + col) = make_float2(v0, v1);
                *(float2*)(ga.C32 + (size_t)wB * ga.cstride + ga.coloff + col) = make_float2(v2, v3);
            }
            if (ga.C16) {
                *(__half2*)(ga.C16 + (size_t)rA * ga.cstride + col) = __floats2half2_rn(v0, v1);
                *(__half2*)(ga.C16 + (size_t)rB * ga.cstride + col) = __floats2half2_rn(v2, v3);
            }
            if (ga.C16b) {
                *(__half2*)(ga.C16b + (size_t)rAm * ga.cstride + col) = __floats2half2_rn(v0, v1);
                *(__half2*)(ga.C16b + (size_t)rBm * ga.cstride + col) = __floats2half2_rn(v2, v3);
            }
        }
    }
}

// ---------------------------------------------------------------------------
// weight transpose+convert. perm=1 (hg weights): output row n' interleaves
// hidden/gate: n<HI -> 2n, else 2(n-HI)+1, so GEMM cols pair (hid_c, gate_c).
// ---------------------------------------------------------------------------
__global__ void wconv_batch_kernel(const float* __restrict__ Wf, const float* __restrict__ Wr,
                                   __half* __restrict__ Tf, __half* __restrict__ Tr,
                                   int K, int N, int perm)
{
    __shared__ float t[32][33];
    int z = blockIdx.z;
    int l = (z >= 3) ? z - 3 : z;
    const float* W = ((z >= 3) ? Wr : Wf) + (size_t)l * K * N;
    __half*      T = ((z >= 3) ? Tr : Tf) + (size_t)l * K * N;
    int n0 = blockIdx.x * 32, k0 = blockIdx.y * 32;
    int tx = threadIdx.x, ty = threadIdx.y;
    for (int r = ty; r < 32; r += 8)
        t[r][tx] = W[(size_t)(k0 + r) * N + n0 + tx];
    __syncthreads();
    for (int r = ty; r < 32; r += 8) {
        int nn = n0 + r;
        int prow = perm ? ((nn < HIsz) ? 2 * nn : 2 * (nn - HIsz) + 1) : nn;
        T[(size_t)prow * K + k0 + tx] = __float2half(t[tx][r]);
    }
}

__global__ void wconv_kernel(const float* __restrict__ W, __half* __restrict__ T,
                             int K, int N)
{
    __shared__ float t[32][33];
    int n0 = blockIdx.x * 32, k0 = blockIdx.y * 32;
    int tx = threadIdx.x, ty = threadIdx.y;
    for (int r = ty; r < 32; r += 8)
        t[r][tx] = W[(size_t)(k0 + r) * N + n0 + tx];
    __syncthreads();
    for (int r = ty; r < 32; r += 8)
        T[(size_t)(n0 + r) * K + k0 + tx] = __float2half(t[tx][r]);
}

__global__ void conv_kernel(const float* __restrict__ x, __half* __restrict__ y, size_t n)
{
    size_t i = ((size_t)blockIdx.x * blockDim.x + threadIdx.x) * 8;
    if (i >= n) return;
    float4 a = *(const float4*)(x + i);
    float4 b = *(const float4*)(x + i + 4);
    struct alignas(16) H8 { __half2 d[4]; } o;
    o.d[0] = __floats2half2_rn(a.x, a.y);
    o.d[1] = __floats2half2_rn(a.z, a.w);
    o.d[2] = __floats2half2_rn(b.x, b.y);
    o.d[3] = __floats2half2_rn(b.z, b.w);
    *(H8*)(y + i) = o;
}

// ---------------------------------------------------------------------------
// Linear scan over (gate, v) pairs: c = sigmoid(-gate) in fp32, h = h*c + v.
// grid (128, 2): x = (b, cblk), y = dir; 128 threads = 128 channels.
// Stage = 16 steps x 128 ch x 4B = 8KB (128 half2 per step row); 4 stages.
// ---------------------------------------------------------------------------
#define SCT 16
#define SSTAGE_B 8192

__global__ __launch_bounds__(128, 2)
void scan_kernel(const __half* __restrict__ hgF, const __half* __restrict__ hgR,
                 __half* __restrict__ hF, __half* __restrict__ hR)
{
    __shared__ char smem[4 * SSTAGE_B];
    const uint32_t sb = s2u(smem);
    const int tid = threadIdx.x;
    const int b = blockIdx.x >> 3;
    const int cblk = (blockIdx.x & 7) << 7;
    const int c = cblk + tid;
    const int dir = blockIdx.y;

    const __half* hgp = (dir ? hgR : hgF) + (size_t)b * Ssz * 2 * HIsz + 2 * cblk;
    __half* hp = (dir ? hR : hF) + (size_t)b * Ssz * HIsz + c;

    const __half* gsl[4];
    uint32_t ssl[4];
#pragma unroll
    for (int j = 0; j < 4; j++) {
        int lin = tid + 128 * j;        // 0..511
        int u   = lin >> 5;             // step 0..15
        int seg = lin & 31;             // 16B segment of 512B row
        gsl[j] = hgp + (size_t)u * 2 * HIsz + seg * 8;
        ssl[j] = (uint32_t)(u * 512 + seg * 16);
    }

    auto load_stage = [&](int st) {
        uint32_t base = sb + (uint32_t)(st & 3) * SSTAGE_B;
        size_t go = (size_t)st * SCT * 2 * HIsz;
#pragma unroll
        for (int j = 0; j < 4; j++) cp16(base + ssl[j], gsl[j] + go);
        cp_commit();
    };

    load_stage(0);
    load_stage(1);
    load_stage(2);

    const int NST = Ssz / SCT;
    float h = 0.f;
    for (int st = 0; st < NST; st++) {
        cp_wait2();
        __syncthreads();
        if (st + 3 < NST) load_stage(st + 3);

        const __half2* base = (const __half2*)(smem + (size_t)(st & 3) * SSTAGE_B);
#pragma unroll
        for (int u = 0; u < SCT; u++) {
            float2 gv = __half22float2(base[u * 128 + tid]);   // (gate, v)
            float cc = __fdividef(1.f, 1.f + __expf(gv.x));    // c = sigmoid(-gate), fp32
            h = fmaf(h, cc, gv.y);
            hp[(size_t)(st * SCT + u) * HIsz] = __float2half(h);
        }
    }
}

// ---------------------------------------------------------------------------
__global__ void seq_kernel(const float* __restrict__ out, const int* __restrict__ lens,
                           float* __restrict__ seq)
{
    int b = blockIdx.x;
    int len = lens[b];
    const float* row = out + ((size_t)b * Ssz + (len - 1)) * 2 * Hsz;
    for (int j = threadIdx.x; j < 2 * Hsz; j += blockDim.x)
        seq[(size_t)b * 2 * Hsz + j] = row[j];
}

// ---------------------------------------------------------------------------
extern "C" void kernel_launch(void* const* d_in, const int* in_sizes, int n_in,
                              void* d_out, int out_size)
{
    const int*   x_source  = (const int*)  d_in[0];
    const int*   x_lengths = (const int*)  d_in[1];
    const float* emb       = (const float*)d_in[2];
    const float* W_er      = (const float*)d_in[3];
    const float* b_er      = (const float*)d_in[4];
    const float* Whg_f     = (const float*)d_in[5];
    const float* Wout_f    = (const float*)d_in[6];
    const float* Whg_r     = (const float*)d_in[7];
    const float* Wout_r    = (const float*)d_in[8];
    float* out = (float*)d_out;

    __half *x16f, *x16r, *hg16f, *hg16r, *h16f, *h16r, *emb16, *w16;
    cudaGetSymbolAddress((void**)&x16f,  g_x16f);
    cudaGetSymbolAddress((void**)&x16r,  g_x16r);
    cudaGetSymbolAddress((void**)&hg16f, g_hg16f);
    cudaGetSymbolAddress((void**)&hg16r, g_hg16r);
    cudaGetSymbolAddress((void**)&h16f,  g_h16f);
    cudaGetSymbolAddress((void**)&h16r,  g_h16r);
    cudaGetSymbolAddress((void**)&emb16, g_emb16);
    cudaGetSymbolAddress((void**)&w16,   g_w16);

    cudaFuncSetAttribute(gemm_kernel, cudaFuncAttributeMaxDynamicSharedMemorySize, GSM);

    // weight converts (hg permuted for (hid,gate) pairing)
    wconv_batch_kernel<<<dim3(2 * HIsz / 32, Hsz / 32, 6), dim3(32, 8)>>>(
        Whg_f, Whg_r, w16 + OFF_HGF, w16 + OFF_HGR, Hsz, 2 * HIsz, 1);
    wconv_batch_kernel<<<dim3(Hsz / 32, HIsz / 32, 6), dim3(32, 8)>>>(
        Wout_f, Wout_r, w16 + OFF_OUTF, w16 + OFF_OUTR, HIsz, Hsz, 0);
    wconv_kernel<<<dim3(Hsz / 32, Esz / 32), dim3(32, 8)>>>(W_er, w16 + OFF_ER, Esz, Hsz);
    conv_kernel<<<(unsigned)(((size_t)Vsz * Esz) / 2048), 256>>>(emb, emb16, (size_t)Vsz * Esz);

    // embed GEMM -> x16f and rev-rotated x16r (fused)
    {
        GArgs a0 = { emb16, w16 + OFF_ER, nullptr, x16f, x16r, b_er, x_source, x_lengths,
                     Hsz, 0, 0, 0 };
        gemm_kernel<<<dim3(Hsz / 128, Msz / 128, 1), GT, GSM>>>(a0, a0, Hsz, Esz);
    }

    for (int l = 0; l < Lsz; l++) {
        bool last = (l == Lsz - 1);
        // gate GEMMs with scan-prep epilogue (both dirs)
        {
            GArgs a0 = { x16f, w16 + OFF_HGF + (size_t)l * 1048576, nullptr, hg16f, nullptr,
                         nullptr, nullptr, nullptr, 2 * HIsz, 0, 0, 1 };
            GArgs a1 = { x16r, w16 + OFF_HGR + (size_t)l * 1048576, nullptr, hg16r, nullptr,
                         nullptr, nullptr, nullptr, 2 * HIsz, 0, 0, 1 };
            gemm_kernel<<<dim3(2 * HIsz / 128, Msz / 128, 2), GT, GSM>>>(a0, a1, 2 * HIsz, Hsz);
        }
        // scans (both dirs)
        scan_kernel<<<dim3(128, 2), 128>>>(hg16f, hg16r, h16f, h16r);
        // output GEMMs (both dirs)
        if (!last) {
            GArgs a0 = { h16f, w16 + OFF_OUTF + (size_t)l * 524288, nullptr, x16f, nullptr,
                         nullptr, nullptr, nullptr, Hsz, 0, 0, 0 };
            GArgs a1 = { h16r, w16 + OFF_OUTR + (size_t)l * 524288, nullptr, x16r, nullptr,
                         nullptr, nullptr, nullptr, Hsz, 0, 0, 0 };
            gemm_kernel<<<dim3(Hsz / 128, Msz / 128, 2), GT, GSM>>>(a0, a1, Hsz, HIsz);
        } else {
            GArgs a0 = { h16f, w16 + OFF_OUTF + (size_t)l * 524288, out, nullptr, nullptr,
                         nullptr, nullptr, x_lengths, 2 * Hsz, 0, 0, 0 };
            GArgs a1 = { h16r, w16 + OFF_OUTR + (size_t)l * 524288, out, nullptr, nullptr,
                         nullptr, nullptr, x_lengths, 2 * Hsz, Hsz, 1, 0 };
            gemm_kernel<<<dim3(Hsz / 128, Msz / 128, 2), GT, GSM>>>(a0, a1, Hsz, HIsz);
        }
    }

    long long need = (long long)Msz * 2 * Hsz + (long long)Bsz * 2 * Hsz;
    if ((long long)out_size >= need)
        seq_kernel<<<Bsz, 256>>>(out, x_lengths, out + (size_t)Msz * 2 * Hsz);
}

// round 11
// speedup vs baseline: 1.0975x; 1.0381x over previous
#include <cuda_runtime.h>
#include <cuda_fp16.h>
#include <math.h>
#include <stdint.h>

// Problem constants
#define Bsz  16
#define Ssz  2048
#define Esz  512
#define Hsz  512
#define HIsz 1024
#define Lsz  3
#define Msz  (Bsz * Ssz)
#define Vsz  32000

// ---------------------------------------------------------------------------
// Scratch (__device__ globals; allocation-free)
// ---------------------------------------------------------------------------
__device__ __half g_x16f[(size_t)Msz * Hsz];
__device__ __half g_x16r[(size_t)Msz * Hsz];
__device__ __half g_hg16f[(size_t)Msz * 2 * HIsz];   // (gate, g) interleaved pairs
__device__ __half g_hg16r[(size_t)Msz * 2 * HIsz];
__device__ __half g_h16f[(size_t)Msz * HIsz];
__device__ __half g_h16r[(size_t)Msz * HIsz];
__device__ __half g_emb16[(size_t)Vsz * Esz];
#define NWELEM 9699328
__device__ __half g_w16[NWELEM];

#define OFF_ER    0
#define OFF_HGF   262144
#define OFF_OUTF  3407872
#define OFF_HGR   4980736
#define OFF_OUTR  8126464

// ---------------------------------------------------------------------------
// PTX helpers (baseline sm_103 ISA only)
// ---------------------------------------------------------------------------
__device__ __forceinline__ uint32_t s2u(const void* p) {
    uint32_t a;
    asm("{ .reg .u64 t; cvta.to.shared.u64 t, %1; cvt.u32.u64 %0, t; }" : "=r"(a) : "l"(p));
    return a;
}
__device__ __forceinline__ void cp16(uint32_t d, const void* s) {
    asm volatile("cp.async.cg.shared.global [%0], [%1], 16;" :: "r"(d), "l"(s));
}
__device__ __forceinline__ void cp_commit() { asm volatile("cp.async.commit_group;"); }
__device__ __forceinline__ void cp_wait2()  { asm volatile("cp.async.wait_group 2;"); }
__device__ __forceinline__ void ldm_x4(uint32_t addr, uint32_t& r0, uint32_t& r1,
                                       uint32_t& r2, uint32_t& r3) {
    asm volatile("ldmatrix.sync.aligned.m8n8.x4.shared.b16 {%0,%1,%2,%3}, [%4];"
                 : "=r"(r0), "=r"(r1), "=r"(r2), "=r"(r3) : "r"(addr));
}
__device__ __forceinline__ void mma_fp16(float& c0, float& c1, float& c2, float& c3,
                                         uint32_t a0, uint32_t a1, uint32_t a2, uint32_t a3,
                                         uint32_t b0, uint32_t b1) {
    asm volatile("mma.sync.aligned.m16n8k16.row.col.f32.f16.f16.f32 "
                 "{%0,%1,%2,%3}, {%4,%5,%6,%7}, {%8,%9}, {%0,%1,%2,%3};"
                 : "+f"(c0), "+f"(c1), "+f"(c2), "+f"(c3)
                 : "r"(a0), "r"(a1), "r"(a2), "r"(a3), "r"(b0), "r"(b1));
}

__device__ __forceinline__ int revrow(int r, int len) {
    int s = r & (Ssz - 1);
    int t = s + Ssz - len; if (t >= Ssz) t -= Ssz;
    return (r & ~(Ssz - 1)) + (Ssz - 1 - t);
}

// (hid, gate) -> (gate, g(hid)); z and the recurrence stay fp32 in the scan
__device__ __forceinline__ float2 scanprep(float hid, float gate) {
    float g = (hid >= 0.f) ? (hid + 0.5f) : __fdividef(1.f, 1.f + __expf(-hid));
    return make_float2(gate, g);
}

// ---------------------------------------------------------------------------
// GEMM problem descriptor (N,K embedded so two different shapes can share
// one launch)
// ---------------------------------------------------------------------------
struct GArgs {
    const __half* A;
    const __half* B;
    float*        C32;
    __half*       C16;
    __half*       C16b;
    const float*  bias;
    const int*    rowidx;
    const int*    lens;
    int cstride;
    int coloff;
    int c32rev;
    int sprep;
    int N;
    int K;
};

#define GT 256
#define ROWB 80
#define TILE_B (128 * ROWB)
#define STAGE_B (2 * TILE_B)
#define GSM (4 * STAGE_B)          // 81920 B dynamic smem (scan uses 64KB of it)

// ---------------------------------------------------------------------------
// gemm body (round-6 config, unchanged math): tile 128x128, BK=32, 8 warps
// ---------------------------------------------------------------------------
__device__ __forceinline__ void gemm_body(const GArgs& ga, int bx, int by, char* smem)
{
    const uint32_t sbase = s2u(smem);
    const int tid = threadIdx.x;
    const int wid = tid >> 5, lid = tid & 31;
    const int bm = by * 128, bn = bx * 128;
    const int wm = (wid & 1) * 64;
    const int wn = (wid >> 1) * 32;
    const int K = ga.K, N = ga.N;

    const __half* gsrc[4];
    uint32_t soff[4];
#pragma unroll
    for (int j = 0; j < 4; j++) {
        int cidx = tid + j * GT;
        int tile = cidx >> 9;
        int idx  = cidx & 511;
        int row  = idx >> 2;
        int seg  = idx & 3;
        soff[j] = (uint32_t)(tile * TILE_B + row * ROWB + seg * 16);
        if (tile == 0) {
            long ra = ga.rowidx ? (long)ga.rowidx[bm + row] : (long)(bm + row);
            gsrc[j] = ga.A + ra * (long)K + seg * 8;
        } else {
            gsrc[j] = ga.B + (long)(bn + row) * K + seg * 8;
        }
    }

    uint32_t aoff[4];
#pragma unroll
    for (int mt = 0; mt < 4; mt++) {
        int r = wm + mt * 16 + (lid & 15);
        int c = (lid >> 4) * 8;
        aoff[mt] = (uint32_t)(r * ROWB + c * 2);
    }
    uint32_t boff[2];
#pragma unroll
    for (int np = 0; np < 2; np++) {
        int r = wn + np * 16 + (lid & 7) + ((lid >> 4) << 3);
        int c = ((lid >> 3) & 1) * 8;
        boff[np] = (uint32_t)(TILE_B + r * ROWB + c * 2);
    }

    float acc[4][4][4];
#pragma unroll
    for (int i = 0; i < 4; i++)
#pragma unroll
        for (int j = 0; j < 4; j++)
#pragma unroll
            for (int q = 0; q < 4; q++) acc[i][j][q] = 0.f;

    const int nst = K >> 5;

    auto load_stage = [&](int s) {
        uint32_t base = sbase + (uint32_t)(s & 3) * STAGE_B;
        int ko = s << 5;
#pragma unroll
        for (int j = 0; j < 4; j++) cp16(base + soff[j], gsrc[j] + ko);
    };

    load_stage(0); cp_commit();
    load_stage(1); cp_commit();
    load_stage(2); cp_commit();

    for (int s = 0; s < nst; s++) {
        cp_wait2();
        __syncthreads();
        if (s + 3 < nst) load_stage(s + 3);
        cp_commit();

        uint32_t base = sbase + (uint32_t)(s & 3) * STAGE_B;
#pragma unroll
        for (int k16 = 0; k16 < 2; k16++) {
            uint32_t koff = (uint32_t)(k16 * 32);
            uint32_t af[4][4];
#pragma unroll
            for (int mt = 0; mt < 4; mt++)
                ldm_x4(base + aoff[mt] + koff, af[mt][0], af[mt][1], af[mt][2], af[mt][3]);
            uint32_t bf[4][2];
#pragma unroll
            for (int np = 0; np < 2; np++) {
                uint32_t r0, r1, r2, r3;
                ldm_x4(base + boff[np] + koff, r0, r1, r2, r3);
                bf[np * 2][0] = r0;     bf[np * 2][1] = r1;
                bf[np * 2 + 1][0] = r2; bf[np * 2 + 1][1] = r3;
            }
#pragma unroll
            for (int mt = 0; mt < 4; mt++)
#pragma unroll
                for (int nt = 0; nt < 4; nt++)
                    mma_fp16(acc[mt][nt][0], acc[mt][nt][1], acc[mt][nt][2], acc[mt][nt][3],
                             af[mt][0], af[mt][1], af[mt][2], af[mt][3],
                             bf[nt][0], bf[nt][1]);
        }
    }

    int len = ga.lens ? ga.lens[bm >> 11] : 0;
#pragma unroll
    for (int mt = 0; mt < 4; mt++) {
        int rA = bm + wm + mt * 16 + (lid >> 2);
        int rB = rA + 8;
        int rAm = ga.lens ? revrow(rA, len) : 0;
        int rBm = ga.lens ? revrow(rB, len) : 0;
#pragma unroll
        for (int nt = 0; nt < 4; nt++) {
            int col = bn + wn + nt * 8 + (lid & 3) * 2;
            float v0 = acc[mt][nt][0], v1 = acc[mt][nt][1];
            float v2 = acc[mt][nt][2], v3 = acc[mt][nt][3];
            if (ga.bias) {
                float2 bb = *(const float2*)(ga.bias + col);
                v0 += bb.x; v1 += bb.y; v2 += bb.x; v3 += bb.y;
            }
            if (ga.sprep) {
                float2 cv0 = scanprep(v0, v1);
                float2 cv1 = scanprep(v2, v3);
                v0 = cv0.x; v1 = cv0.y; v2 = cv1.x; v3 = cv1.y;
            }
            if (ga.C32) {
                int wA = ga.c32rev ? rAm : rA;
                int wB = ga.c32rev ? rBm : rB;
                *(float2*)(ga.C32 + (size_t)wA * ga.cstride + ga.coloff + col) = make_float2(v0, v1);
                *(float2*)(ga.C32 + (size_t)wB * ga.cstride + ga.coloff + col) = make_float2(v2, v3);
            }
            if (ga.C16) {
                *(__half2*)(ga.C16 + (size_t)rA * ga.cstride + col) = __floats2half2_rn(v0, v1);
                *(__half2*)(ga.C16 + (size_t)rB * ga.cstride + col) = __floats2half2_rn(v2, v3);
            }
            if (ga.C16b) {
                *(__half2*)(ga.C16b + (size_t)rAm * ga.cstride + col) = __floats2half2_rn(v0, v1);
                *(__half2*)(ga.C16b + (size_t)rBm * ga.cstride + col) = __floats2half2_rn(v2, v3);
            }
        }
    }
}

// ---------------------------------------------------------------------------
// scan body: 256 threads = 256 channels; 64 blocks per direction.
// (gate,g) fp16 pairs in; h fp16 out. z and recurrence in fp32.
// Stage = 16 steps x 256 ch x 4B = 16KB; 4 stages in the gemm's dyn smem.
// ---------------------------------------------------------------------------
#define SCT 16
#define SSTAGE_B 16384

__device__ __forceinline__ void scan_body(const __half* __restrict__ hg,
                                          __half* __restrict__ h,
                                          int sid, char* smem)
{
    const uint32_t sb = s2u(smem);
    const int tid = threadIdx.x;
    const int b = sid >> 2;
    const int cblk = (sid & 3) << 8;              // 256-channel block

    const __half* hgp = hg + (size_t)b * Ssz * 2 * HIsz + 2 * cblk;
    __half* hp = h + (size_t)b * Ssz * HIsz + cblk + tid;

    const __half* gsl[4];
    uint32_t ssl[4];
#pragma unroll
    for (int j = 0; j < 4; j++) {
        int lin = tid + 256 * j;                  // 0..1023
        int u   = lin >> 6;                       // step 0..15
        int seg = lin & 63;                       // 16B segment of 1KB row
        gsl[j] = hgp + (size_t)u * 2 * HIsz + seg * 8;
        ssl[j] = (uint32_t)(u * 1024 + seg * 16);
    }

    auto load_stage = [&](int st) {
        uint32_t base = sb + (uint32_t)(st & 3) * SSTAGE_B;
        size_t go = (size_t)st * SCT * 2 * HIsz;
#pragma unroll
        for (int j = 0; j < 4; j++) cp16(base + ssl[j], gsl[j] + go);
        cp_commit();
    };

    load_stage(0);
    load_stage(1);
    load_stage(2);

    const int NST = Ssz / SCT;
    float hv = 0.f;
    for (int st = 0; st < NST; st++) {
        cp_wait2();
        __syncthreads();
        if (st + 3 < NST) load_stage(st + 3);

        const __half2* base = (const __half2*)(smem + (size_t)(st & 3) * SSTAGE_B);
#pragma unroll
        for (int u = 0; u < SCT; u++) {
            float2 gg = __half22float2(base[u * 256 + tid]);     // (gate, g)
            float z = __fdividef(1.f, 1.f + __expf(-gg.x));      // fp32 sigmoid
            hv += z * (gg.y - hv);
            hp[(size_t)(st * SCT + u) * HIsz] = __float2half(hv);
        }
    }
}

// ---------------------------------------------------------------------------
// mega kernel: [scan blocks][gemm problem 0 blocks][gemm problem 1 blocks]
// ---------------------------------------------------------------------------
__global__ __launch_bounds__(GT, 2)
void mega_kernel(GArgs ga0, GArgs ga1, int nscan, int nb0, int nx0, int nx1,
                 const __half* sHG, __half* sH)
{
    extern __shared__ char smem[];
    int bid = blockIdx.x;
    if (bid < nscan) { scan_body(sHG, sH, bid, smem); return; }
    bid -= nscan;
    if (bid < nb0) {
        gemm_body(ga0, bid % nx0, bid / nx0, smem);
    } else {
        bid -= nb0;
        gemm_body(ga1, bid % nx1, bid / nx1, smem);
    }
}

// ---------------------------------------------------------------------------
// weight transpose+convert (perm=1: interleave hidden/gate output rows)
// ---------------------------------------------------------------------------
__global__ void wconv_batch_kernel(const float* __restrict__ Wf, const float* __restrict__ Wr,
                                   __half* __restrict__ Tf, __half* __restrict__ Tr,
                                   int K, int N, int perm)
{
    __shared__ float t[32][33];
    int z = blockIdx.z;
    int l = (z >= 3) ? z - 3 : z;
    const float* W = ((z >= 3) ? Wr : Wf) + (size_t)l * K * N;
    __half*      T = ((z >= 3) ? Tr : Tf) + (size_t)l * K * N;
    int n0 = blockIdx.x * 32, k0 = blockIdx.y * 32;
    int tx = threadIdx.x, ty = threadIdx.y;
    for (int r = ty; r < 32; r += 8)
        t[r][tx] = W[(size_t)(k0 + r) * N + n0 + tx];
    __syncthreads();
    for (int r = ty; r < 32; r += 8) {
        int nn = n0 + r;
        int prow = perm ? ((nn < HIsz) ? 2 * nn : 2 * (nn - HIsz) + 1) : nn;
        T[(size_t)prow * K + k0 + tx] = __float2half(t[tx][r]);
    }
}

__global__ void wconv_kernel(const float* __restrict__ W, __half* __restrict__ T,
                             int K, int N)
{
    __shared__ float t[32][33];
    int n0 = blockIdx.x * 32, k0 = blockIdx.y * 32;
    int tx = threadIdx.x, ty = threadIdx.y;
    for (int r = ty; r < 32; r += 8)
        t[r][tx] = W[(size_t)(k0 + r) * N + n0 + tx];
    __syncthreads();
    for (int r = ty; r < 32; r += 8)
        T[(size_t)(n0 + r) * K + k0 + tx] = __float2half(t[tx][r]);
}

__global__ void conv_kernel(const float* __restrict__ x, __half* __restrict__ y, size_t n)
{
    size_t i = ((size_t)blockIdx.x * blockDim.x + threadIdx.x) * 8;
    if (i >= n) return;
    float4 a = *(const float4*)(x + i);
    float4 b = *(const float4*)(x + i + 4);
    struct alignas(16) H8 { __half2 d[4]; } o;
    o.d[0] = __floats2half2_rn(a.x, a.y);
    o.d[1] = __floats2half2_rn(a.z, a.w);
    o.d[2] = __floats2half2_rn(b.x, b.y);
    o.d[3] = __floats2half2_rn(b.z, b.w);
    *(H8*)(y + i) = o;
}

__global__ void seq_kernel(const float* __restrict__ out, const int* __restrict__ lens,
                           float* __restrict__ seq)
{
    int b = blockIdx.x;
    int len = lens[b];
    const float* row = out + ((size_t)b * Ssz + (len - 1)) * 2 * Hsz;
    for (int j = threadIdx.x; j < 2 * Hsz; j += blockDim.x)
        seq[(size_t)b * 2 * Hsz + j] = row[j];
}

// ---------------------------------------------------------------------------
extern "C" void kernel_launch(void* const* d_in, const int* in_sizes, int n_in,
                              void* d_out, int out_size)
{
    const int*   x_source  = (const int*)  d_in[0];
    const int*   x_lengths = (const int*)  d_in[1];
    const float* emb       = (const float*)d_in[2];
    const float* W_er      = (const float*)d_in[3];
    const float* b_er      = (const float*)d_in[4];
    const float* Whg_f     = (const float*)d_in[5];
    const float* Wout_f    = (const float*)d_in[6];
    const float* Whg_r     = (const float*)d_in[7];
    const float* Wout_r    = (const float*)d_in[8];
    float* out = (float*)d_out;

    __half *x16f, *x16r, *hg16f, *hg16r, *h16f, *h16r, *emb16, *w16;
    cudaGetSymbolAddress((void**)&x16f,  g_x16f);
    cudaGetSymbolAddress((void**)&x16r,  g_x16r);
    cudaGetSymbolAddress((void**)&hg16f, g_hg16f);
    cudaGetSymbolAddress((void**)&hg16r, g_hg16r);
    cudaGetSymbolAddress((void**)&h16f,  g_h16f);
    cudaGetSymbolAddress((void**)&h16r,  g_h16r);
    cudaGetSymbolAddress((void**)&emb16, g_emb16);
    cudaGetSymbolAddress((void**)&w16,   g_w16);

    cudaFuncSetAttribute(mega_kernel, cudaFuncAttributeMaxDynamicSharedMemorySize, GSM);

    const int HG_NB = 16 * 256, HG_NX = 16;      // N=2048 gemm
    const int OUT_NB = 4 * 256, OUT_NX = 4;      // N=512 gemm
    const int NSCAN = 64;

    // prologue: weight/table converts
    wconv_batch_kernel<<<dim3(2 * HIsz / 32, Hsz / 32, 6), dim3(32, 8)>>>(
        Whg_f, Whg_r, w16 + OFF_HGF, w16 + OFF_HGR, Hsz, 2 * HIsz, 1);
    wconv_batch_kernel<<<dim3(Hsz / 32, HIsz / 32, 6), dim3(32, 8)>>>(
        Wout_f, Wout_r, w16 + OFF_OUTF, w16 + OFF_OUTR, HIsz, Hsz, 0);
    wconv_kernel<<<dim3(Hsz / 32, Esz / 32), dim3(32, 8)>>>(W_er, w16 + OFF_ER, Esz, Hsz);
    conv_kernel<<<(unsigned)(((size_t)Vsz * Esz) / 2048), 256>>>(emb, emb16, (size_t)Vsz * Esz);

    auto HG = [&](int l, int dir) {   // gate gemm args
        GArgs a = { dir ? x16r : x16f,
                    w16 + (dir ? OFF_HGR : OFF_HGF) + (size_t)l * 1048576,
                    nullptr, dir ? hg16r : hg16f, nullptr, nullptr, nullptr, nullptr,
                    2 * HIsz, 0, 0, 1, 2 * HIsz, Hsz };
        return a;
    };
    auto OUTm = [&](int l, int dir) { // mid-layer out gemm args
        GArgs a = { dir ? h16r : h16f,
                    w16 + (dir ? OFF_OUTR : OFF_OUTF) + (size_t)l * 524288,
                    nullptr, dir ? x16r : x16f, nullptr, nullptr, nullptr, nullptr,
                    Hsz, 0, 0, 0, Hsz, HIsz };
        return a;
    };
    auto OUTf = [&](int dir) {        // final out gemm -> fp32 out
        GArgs a = { dir ? h16r : h16f,
                    w16 + (dir ? OFF_OUTR : OFF_OUTF) + (size_t)2 * 524288,
                    out, nullptr, nullptr, nullptr, nullptr, x_lengths,
                    2 * Hsz, dir ? Hsz : 0, dir ? 1 : 0, 0, Hsz, HIsz };
        return a;
    };

    // embed GEMM -> x16f and rev-rotated x16r (fused epilogue)
    {
        GArgs a = { emb16, w16 + OFF_ER, nullptr, x16f, x16r, b_er, x_source, x_lengths,
                    Hsz, 0, 0, 0, Hsz, Esz };
        mega_kernel<<<OUT_NB, GT, GSM>>>(a, a, 0, OUT_NB, OUT_NX, OUT_NX, nullptr, nullptr);
    }

    // software-pipelined dual chains: scans hidden under the other chain's GEMM
    // L1:  hgF0
    {
        GArgs a = HG(0, 0);
        mega_kernel<<<HG_NB, GT, GSM>>>(a, a, 0, HG_NB, HG_NX, HG_NX, nullptr, nullptr);
    }
    for (int l = 0; l < Lsz; l++) {
        // hgR(l) ∥ scanF(l)
        {
            GArgs a = HG(l, 1);
            mega_kernel<<<NSCAN + HG_NB, GT, GSM>>>(a, a, NSCAN, HG_NB, HG_NX, HG_NX,
                                                    hg16f, h16f);
        }
        // outF(l) ∥ scanR(l)
        {
            GArgs a = (l == Lsz - 1) ? OUTf(0) : OUTm(l, 0);
            mega_kernel<<<NSCAN + OUT_NB, GT, GSM>>>(a, a, NSCAN, OUT_NB, OUT_NX, OUT_NX,
                                                     hg16r, h16r);
        }
        if (l + 1 < Lsz) {
            // hgF(l+1) ∥ outR(l)
            GArgs a0 = HG(l + 1, 0);
            GArgs a1 = OUTm(l, 1);
            mega_kernel<<<HG_NB + OUT_NB, GT, GSM>>>(a0, a1, 0, HG_NB, HG_NX, OUT_NX,
                                                     nullptr, nullptr);
        } else {
            // outR(last) -> fp32 out (rev row-mapped, cols [H,2H))
            GArgs a = OUTf(1);
            mega_kernel<<<OUT_NB, GT, GSM>>>(a, a, 0, OUT_NB, OUT_NX, OUT_NX,
                                             nullptr, nullptr);
        }
    }

    long long need = (long long)Msz * 2 * Hsz + (long long)Bsz * 2 * Hsz;
    if ((long long)out_size >= need)
        seq_kernel<<<Bsz, 256>>>(out, x_lengths, out + (size_t)Msz * 2 * Hsz);
}